// round 10
// baseline (speedup 1.0000x reference)
#include <cuda_runtime.h>
#include <math.h>

// ---------------------------------------------------------------------------
// GaussianSplattingCompliance: N_POINTS=131072, N_G=256
// s = sigmoid(-10(z-1)). With y = K(z-1), K = 10*log2(e), u = 2^(-|y|):
//   s = 0.5 - copysign(r, y),  r(u) = 0.5 - u*h(u),  h(u) = 1/(1+u)
// h approximated by degree-6 poly (err ~8e-6); exact as u->0 (no bias).
// Affine precompute absorbs K: u1 = A1*cx+B1*cy+C1 etc, sqrt(uu+vv) == K*z.
// ks = sum s + 1e-8 = 128 - sum copysign(r,y) + 1e-8.
// ---------------------------------------------------------------------------

#define N_POINTS 131072
#define N_G      256
#define PRE_BLOCKS 256
#define KK 14.4269504088896341f    // 10 * log2(e)

__device__ unsigned g_enc[4];
__device__ unsigned g_count;
__device__ float4   g_AB[N_G];
__device__ float2   g_C[N_G];

__device__ __forceinline__ unsigned f_enc(float f) {
    unsigned u = __float_as_uint(f);
    return (u & 0x80000000u) ? ~u : (u | 0x80000000u);
}
__device__ __forceinline__ float f_dec(unsigned e) {
    unsigned u = (e & 0x80000000u) ? (e ^ 0x80000000u) : ~e;
    return __uint_as_float(u);
}
__device__ __forceinline__ float sigmoid_f(float x) {
    return 1.0f / (1.0f + expf(-x));
}

// ---------------- fused prologue: minmax + params + scratch reset -----------
__global__ void __launch_bounds__(256)
gs_pre_kernel(const float4* __restrict__ coords4,
              const float*  __restrict__ W_scale,
              const float*  __restrict__ W_shape_var,
              const float*  __restrict__ W_rotation,
              const float2* __restrict__ W_offsets) {
    __shared__ float s_red[8][4];
    __shared__ int   s_last;
    int tid = threadIdx.x;

    float4 q = coords4[blockIdx.x * 256 + tid];
    float mxx = fmaxf(q.x, q.z), mxy = fmaxf(q.y, q.w);
    float nmx = -fminf(q.x, q.z), nmy = -fminf(q.y, q.w);

    #pragma unroll
    for (int o = 16; o > 0; o >>= 1) {
        mxx = fmaxf(mxx, __shfl_xor_sync(0xffffffffu, mxx, o));
        mxy = fmaxf(mxy, __shfl_xor_sync(0xffffffffu, mxy, o));
        nmx = fmaxf(nmx, __shfl_xor_sync(0xffffffffu, nmx, o));
        nmy = fmaxf(nmy, __shfl_xor_sync(0xffffffffu, nmy, o));
    }
    int wid = tid >> 5, lid = tid & 31;
    if (lid == 0) {
        s_red[wid][0] = mxx; s_red[wid][1] = mxy;
        s_red[wid][2] = nmx; s_red[wid][3] = nmy;
    }
    __syncthreads();
    if (tid == 0) {
        float a = s_red[0][0], b = s_red[0][1], c = s_red[0][2], d = s_red[0][3];
        #pragma unroll
        for (int w = 1; w < 8; w++) {
            a = fmaxf(a, s_red[w][0]); b = fmaxf(b, s_red[w][1]);
            c = fmaxf(c, s_red[w][2]); d = fmaxf(d, s_red[w][3]);
        }
        atomicMax(&g_enc[0], f_enc(a));
        atomicMax(&g_enc[1], f_enc(b));
        atomicMax(&g_enc[2], f_enc(c));
        atomicMax(&g_enc[3], f_enc(d));
        __threadfence();
        unsigned done = atomicAdd(&g_count, 1u);
        s_last = (done == PRE_BLOCKS - 1) ? 1 : 0;
    }
    __syncthreads();
    if (!s_last) return;

    float cmaxx = f_dec(atomicMax(&g_enc[0], 0u));
    float cmaxy = f_dec(atomicMax(&g_enc[1], 0u));
    float cminx = -f_dec(atomicMax(&g_enc[2], 0u));
    float cminy = -f_dec(atomicMax(&g_enc[3], 0u));

    float lo_x = cminx - cmaxx * 0.05f, hi_x = cmaxx + cmaxx * 0.05f;
    float lo_y = cminy - cmaxy * 0.05f, hi_y = cmaxy + cmaxy * 0.05f;

    int b = tid;
    float base_scale = (1.5f - 0.05f) * sigmoid_f(W_scale[b]) + 0.05f;
    float ratio      = (3.5f - 0.5f) * sigmoid_f(W_shape_var[b]) + 0.5f;
    const float PI_F = 3.14159265358979323846f;
    float rot        = -0.5f * PI_F + PI_F * sigmoid_f(W_rotation[b]);
    float2 wo = W_offsets[b];
    float ox = lo_x + (hi_x - lo_x) * sigmoid_f(wo.x);
    float oy = lo_y + (hi_y - lo_y) * sigmoid_f(wo.y);

    float inv_s = 1.0f / (base_scale + 1e-8f);
    float sq0 = sqrtf(1.0f / (1.0f + 1e-6f));
    float sq1 = sqrtf(1.0f / (ratio * ratio + 1e-6f));
    float c = cosf(rot), s = sinf(rot);

    float k0 = KK * inv_s * sq0;     // absorb K = 10*log2(e)
    float k1 = KK * inv_s * sq1;
    float A1 =  c * k0, B1 = -s * k0;
    float A2 =  s * k1, B2 =  c * k1;
    float C1 = -(A1 * ox + B1 * oy);
    float C2 = -(A2 * ox + B2 * oy);

    g_AB[b] = make_float4(A1, B1, A2, B2);
    g_C[b]  = make_float2(C1, C2);

    if (tid < 4) g_enc[tid] = 0u;
    if (tid == 0) g_count = 0u;
}

// ------- main kernel: 2 threads/point (split gaussians), f32x2 math ---------

#define FMA2(d, a, b, c) \
    asm("fma.rn.f32x2 %0, %1, %2, %3;" : "=l"(d) : "l"(a), "l"(b), "l"(c))
#define MUL2(d, a, b) \
    asm("mul.rn.f32x2 %0, %1, %2;" : "=l"(d) : "l"(a), "l"(b))
#define PACK2(d, lo, hi) \
    asm("mov.b64 %0, {%1, %2};" : "=l"(d) : "f"(lo), "f"(hi))
#define UNPACK2(lo, hi, s) \
    asm("mov.b64 {%0, %1}, %2;" : "=f"(lo), "=f"(hi) : "l"(s))

#define N_PAIR   (N_G / 2)      // 128 gaussian pairs
#define PTS_BLK  128            // points per block
#define HALF_GP  (N_PAIR / 2)   // 64 pairs per thread-half

// H(u) = -h(u) where h approximates 1/(1+u) on [0,1], degree 6.
// r = fma(u, H(u), 0.5) = 0.5 - u*h(u)  ==  0.5*(1-u)/(1+u) + O(8e-6*u)
#define PH0 (-0.999992f)
#define PH1 ( 0.999226f)
#define PH2 (-0.986398f)
#define PH3 ( 0.907098f)
#define PH4 (-0.675364f)
#define PH5 ( 0.329306f)
#define PH6 (-0.073884f)

__global__ void __launch_bounds__(256)
gs_main_kernel(const float2* __restrict__ coords, float* __restrict__ out) {
    __shared__ ulonglong2 sP[N_PAIR * 3];
    __shared__ float s_part[PTS_BLK];
    int t = threadIdx.x;

    if (t < N_PAIR) {
        float4 abE = g_AB[2 * t];
        float4 abO = g_AB[2 * t + 1];
        float2 cE  = g_C[2 * t];
        float2 cO  = g_C[2 * t + 1];
        float4* dst = (float4*)&sP[3 * t];
        dst[0] = make_float4(abE.x, abO.x, abE.y, abO.y);   // A1 pair, B1 pair
        dst[1] = make_float4(abE.z, abO.z, abE.w, abO.w);   // A2 pair, B2 pair
        dst[2] = make_float4(cE.x,  cO.x,  cE.y,  cO.y);    // C1 pair, C2 pair
    }
    __syncthreads();

    int half = t >> 7;                    // 0: pairs 0..63, 1: pairs 64..127
    int tp   = t & (PTS_BLK - 1);
    int i = blockIdx.x * PTS_BLK + tp;
    float2 p = coords[i];
    unsigned long long cxx, cyy;
    PACK2(cxx, p.x, p.x);
    PACK2(cyy, p.y, p.y);

    // packed poly coefficient registers (loop-invariant)
    unsigned long long h0p, h1p, h2p, h3p, h4p, h5p, h6p, halfp;
    PACK2(h0p, PH0, PH0); PACK2(h1p, PH1, PH1);
    PACK2(h2p, PH2, PH2); PACK2(h3p, PH3, PH3);
    PACK2(h4p, PH4, PH4); PACK2(h5p, PH5, PH5);
    PACK2(h6p, PH6, PH6); PACK2(halfp, 0.5f, 0.5f);

    const ulonglong2* pp = &sP[half * HALF_GP * 3];
    float sum0 = 0.0f, sum1 = 0.0f;
    #pragma unroll 8
    for (int gp = 0; gp < HALF_GP; gp++) {
        ulonglong2 q0 = pp[3 * gp + 0];
        ulonglong2 q1 = pp[3 * gp + 1];
        ulonglong2 q2 = pp[3 * gp + 2];
        unsigned long long uu, vv, ss, t1;
        FMA2(t1, q0.y, cyy, q2.x);        // B1*cy + C1
        FMA2(uu, q0.x, cxx, t1);          // A1*cx + ...
        FMA2(t1, q1.y, cyy, q2.y);        // B2*cy + C2
        FMA2(vv, q1.x, cxx, t1);          // A2*cx + ...
        MUL2(t1, vv, vv);
        FMA2(ss, uu, uu, t1);             // {K^2 z^2 even, odd}

        float s0, s1;
        UNPACK2(s0, s1, ss);
        float zp0, zp1;
        asm("sqrt.approx.f32 %0, %1;" : "=f"(zp0) : "f"(s0));
        asm("sqrt.approx.f32 %0, %1;" : "=f"(zp1) : "f"(s1));
        float y0 = zp0 - KK;              // y = K(z-1)
        float y1 = zp1 - KK;
        float m0 = fminf(y0, -y0);        // -|y|
        float m1 = fminf(y1, -y1);
        float e0, e1;
        asm("ex2.approx.f32 %0, %1;" : "=f"(e0) : "f"(m0));   // u = 2^(-|y|)
        asm("ex2.approx.f32 %0, %1;" : "=f"(e1) : "f"(m1));

        unsigned long long up, acc, rr;
        PACK2(up, e0, e1);
        FMA2(acc, h6p, up, h5p);          // Horner on H(u) = -h(u)
        FMA2(acc, acc, up, h4p);
        FMA2(acc, acc, up, h3p);
        FMA2(acc, acc, up, h2p);
        FMA2(acc, acc, up, h1p);
        FMA2(acc, acc, up, h0p);
        FMA2(rr, acc, up, halfp);         // r = 0.5 - u*h(u)

        float r0, r1;
        UNPACK2(r0, r1, rr);
        sum0 += copysignf(r0, y0);
        sum1 += copysignf(r1, y1);
    }

    float mysum = sum0 + sum1;
    if (half) s_part[tp] = mysum;
    __syncthreads();
    if (!half) {
        float tot = mysum + s_part[tp];
        // ks = sum s + 1e-8 = 128 - tot + 1e-8
        float ks = (128.0f - tot) + 1e-8f;
        float e = __expf(10.0f * (ks - 0.5f));
        out[i] = (1.0f - 1e-9f) / (1.0f + e) + 1e-9f;
    }
}

extern "C" void kernel_launch(void* const* d_in, const int* in_sizes, int n_in,
                              void* d_out, int out_size) {
    const float4* coords4     = (const float4*)d_in[0];
    const float2* coords2     = (const float2*)d_in[0];
    const float*  W_scale     = (const float*)d_in[1];
    const float*  W_shape_var = (const float*)d_in[2];
    const float*  W_rotation  = (const float*)d_in[3];
    const float2* W_offsets   = (const float2*)d_in[4];
    float* out = (float*)d_out;

    gs_pre_kernel<<<PRE_BLOCKS, 256>>>(coords4, W_scale, W_shape_var,
                                       W_rotation, W_offsets);
    gs_main_kernel<<<N_POINTS / PTS_BLK, 256>>>(coords2, out);
}

// round 12
// speedup vs baseline: 1.0453x; 1.0453x over previous
#include <cuda_runtime.h>
#include <math.h>

// ---------------------------------------------------------------------------
// GaussianSplattingCompliance: N_POINTS=131072, N_G=256  — single fused kernel
//
// s(z) = sigmoid(-10(z-1)) = 1/(1+e^{10(z-1)}).  Affine absorbs K=10*log2(e):
//   u = A1*cx+B1*cy+C1, v = A2*cx+B2*cy+C2,  zp = sqrt(uu+vv) = K*z
//   e = 2^{min(zp,73.93) - K}  (clamp keeps products finite; saturated -> ~0)
// Pair identity (exact): s0+s1 = (2+e0+e1) * rcp((1+e0)(1+e1))
//   -> MUFU per gaussian: sqrt(8)+ex2(8)+rcp/2(4) = 20 cyc  (was 24)
//
// Phases (one kernel, 512 blocks x 256 thr, all co-resident):
//   1) block-local coord minmax -> global atomics -> spin barrier
//   2) every block computes all 256 gaussian params into ITS OWN shared
//   3) main loop: 1 point/thread, 128 gaussian pairs, packed f32x2 affine
//   4) last block resets scratch (graph-replay safe)
// ---------------------------------------------------------------------------

#define N_POINTS 131072
#define N_G      256
#define N_PAIR   (N_G / 2)
#define GRID     512
#define PTS_BLK  256          // points per block (1 per thread)
#define KK 14.4269504088896341f    // 10 * log2(e)

__device__ unsigned g_enc[4];      // enc(max x), enc(max y), enc(max -x), enc(max -y)
__device__ unsigned g_count;       // phase-1 arrival counter
__device__ unsigned g_count2;      // phase-2 departure counter (for reset)

__device__ __forceinline__ unsigned f_enc(float f) {
    unsigned u = __float_as_uint(f);
    return (u & 0x80000000u) ? ~u : (u | 0x80000000u);
}
__device__ __forceinline__ float f_dec(unsigned e) {
    unsigned u = (e & 0x80000000u) ? (e ^ 0x80000000u) : ~e;
    return __uint_as_float(u);
}
__device__ __forceinline__ float sigmoid_f(float x) {
    return 1.0f / (1.0f + expf(-x));
}

#define FMA2(d, a, b, c) \
    asm("fma.rn.f32x2 %0, %1, %2, %3;" : "=l"(d) : "l"(a), "l"(b), "l"(c))
#define MUL2(d, a, b) \
    asm("mul.rn.f32x2 %0, %1, %2;" : "=l"(d) : "l"(a), "l"(b))
#define PACK2(d, lo, hi) \
    asm("mov.b64 %0, {%1, %2};" : "=l"(d) : "f"(lo), "f"(hi))
#define UNPACK2(lo, hi, s) \
    asm("mov.b64 {%0, %1}, %2;" : "=f"(lo), "=f"(hi) : "l"(s))

__global__ void __launch_bounds__(256, 4)
gs_fused_kernel(const float4* __restrict__ coords4,
                const float2* __restrict__ coords,
                const float*  __restrict__ W_scale,
                const float*  __restrict__ W_shape_var,
                const float*  __restrict__ W_rotation,
                const float2* __restrict__ W_offsets,
                float* __restrict__ out) {
    // pair p (gaussians 2p,2p+1), 12 floats:
    // [A1e,A1o,B1e,B1o, A2e,A2o,B2e,B2o, C1e,C1o,C2e,C2o]
    __shared__ float sP[N_PAIR * 12];
    __shared__ float s_red[4][4];
    __shared__ float s_bounds[4];    // cmaxx, cmaxy, cminx, cminy
    int t = threadIdx.x;

    // ---------- phase 1: block-local minmax over this block's 256 points ----
    if (t < 128) {
        float4 q = coords4[blockIdx.x * 128 + t];
        float mxx = fmaxf(q.x, q.z), mxy = fmaxf(q.y, q.w);
        float nmx = -fminf(q.x, q.z), nmy = -fminf(q.y, q.w);
        #pragma unroll
        for (int o = 16; o > 0; o >>= 1) {
            mxx = fmaxf(mxx, __shfl_xor_sync(0xffffffffu, mxx, o));
            mxy = fmaxf(mxy, __shfl_xor_sync(0xffffffffu, mxy, o));
            nmx = fmaxf(nmx, __shfl_xor_sync(0xffffffffu, nmx, o));
            nmy = fmaxf(nmy, __shfl_xor_sync(0xffffffffu, nmy, o));
        }
        if ((t & 31) == 0) {
            int w = t >> 5;
            s_red[w][0] = mxx; s_red[w][1] = mxy;
            s_red[w][2] = nmx; s_red[w][3] = nmy;
        }
    }
    __syncthreads();
    if (t == 0) {
        float a = s_red[0][0], b = s_red[0][1], c = s_red[0][2], d = s_red[0][3];
        #pragma unroll
        for (int w = 1; w < 4; w++) {
            a = fmaxf(a, s_red[w][0]); b = fmaxf(b, s_red[w][1]);
            c = fmaxf(c, s_red[w][2]); d = fmaxf(d, s_red[w][3]);
        }
        atomicMax(&g_enc[0], f_enc(a));
        atomicMax(&g_enc[1], f_enc(b));
        atomicMax(&g_enc[2], f_enc(c));
        atomicMax(&g_enc[3], f_enc(d));
        __threadfence();
        atomicAdd(&g_count, 1u);
        // spin until all 512 blocks contributed (all blocks co-resident)
        while (atomicAdd(&g_count, 0u) < GRID) { }
        __threadfence();
        s_bounds[0] = f_dec(g_enc[0]);
        s_bounds[1] = f_dec(g_enc[1]);
        s_bounds[2] = -f_dec(g_enc[2]);
        s_bounds[3] = -f_dec(g_enc[3]);
    }
    __syncthreads();

    // ---------- phase 2: every block computes all 256 params into shared ----
    {
        float cmaxx = s_bounds[0], cmaxy = s_bounds[1];
        float cminx = s_bounds[2], cminy = s_bounds[3];
        float lo_x = cminx - cmaxx * 0.05f, hi_x = cmaxx + cmaxx * 0.05f;
        float lo_y = cminy - cmaxy * 0.05f, hi_y = cmaxy + cmaxy * 0.05f;

        int g = t;   // one gaussian per thread
        float base_scale = (1.5f - 0.05f) * sigmoid_f(W_scale[g]) + 0.05f;
        float ratio      = (3.5f - 0.5f) * sigmoid_f(W_shape_var[g]) + 0.5f;
        const float PI_F = 3.14159265358979323846f;
        float rot        = -0.5f * PI_F + PI_F * sigmoid_f(W_rotation[g]);
        float2 wo = W_offsets[g];
        float ox = lo_x + (hi_x - lo_x) * sigmoid_f(wo.x);
        float oy = lo_y + (hi_y - lo_y) * sigmoid_f(wo.y);

        float inv_s = 1.0f / (base_scale + 1e-8f);
        float sq0 = sqrtf(1.0f / (1.0f + 1e-6f));
        float sq1 = sqrtf(1.0f / (ratio * ratio + 1e-6f));
        float cr = cosf(rot), sr = sinf(rot);

        float k0 = KK * inv_s * sq0;        // absorb K = 10*log2(e)
        float k1 = KK * inv_s * sq1;
        float A1 =  cr * k0, B1 = -sr * k0;
        float A2 =  sr * k1, B2 =  cr * k1;
        float C1 = -(A1 * ox + B1 * oy);
        float C2 = -(A2 * ox + B2 * oy);

        int p = g >> 1, o = g & 1;
        float* dst = &sP[12 * p + o];
        dst[0]  = A1; dst[2]  = B1;
        dst[4]  = A2; dst[6]  = B2;
        dst[8]  = C1; dst[10] = C2;

        // departure counter: last block resets global scratch for next replay
        __syncthreads();
        if (t == 0) {
            unsigned done = atomicAdd(&g_count2, 1u);
            if (done == GRID - 1) {
                g_enc[0] = 0u; g_enc[1] = 0u; g_enc[2] = 0u; g_enc[3] = 0u;
                g_count = 0u;
                __threadfence();
                g_count2 = 0u;
            }
        }
    }
    __syncthreads();

    // ---------- phase 3: main loop, 1 point/thread, 128 gaussian pairs ------
    int i = blockIdx.x * PTS_BLK + t;
    float2 pt = coords[i];
    unsigned long long cxx, cyy;
    PACK2(cxx, pt.x, pt.x);
    PACK2(cyy, pt.y, pt.y);

    const ulonglong2* pp = (const ulonglong2*)sP;
    float sumA = 0.0f, sumB = 0.0f;
    #pragma unroll 4
    for (int gp = 0; gp < N_PAIR; gp++) {
        ulonglong2 q0 = pp[3 * gp + 0];   // {A1 pair, B1 pair}
        ulonglong2 q1 = pp[3 * gp + 1];   // {A2 pair, B2 pair}
        ulonglong2 q2 = pp[3 * gp + 2];   // {C1 pair, C2 pair}
        unsigned long long uu, vv, ss, t1;
        FMA2(t1, q0.y, cyy, q2.x);        // B1*cy + C1
        FMA2(uu, q0.x, cxx, t1);          // A1*cx + ...
        FMA2(t1, q1.y, cyy, q2.y);        // B2*cy + C2
        FMA2(vv, q1.x, cxx, t1);          // A2*cx + ...
        MUL2(t1, vv, vv);
        FMA2(ss, uu, uu, t1);             // {K^2 z^2 even, odd}

        float s0, s1;
        UNPACK2(s0, s1, ss);
        float z0, z1;
        asm("sqrt.approx.f32 %0, %1;" : "=f"(z0) : "f"(s0));   // K*z
        asm("sqrt.approx.f32 %0, %1;" : "=f"(z1) : "f"(s1));
        float m0 = fminf(z0, 73.93f) - KK;    // clamp: e <= 2^59.5
        float m1 = fminf(z1, 73.93f) - KK;
        float e0, e1;
        asm("ex2.approx.f32 %0, %1;" : "=f"(e0) : "f"(m0));    // e^{10(z-1)}
        asm("ex2.approx.f32 %0, %1;" : "=f"(e1) : "f"(m1));

        // s0+s1 = (2+e0+e1) * rcp((1+e0)(1+e1))   [exact identity]
        float a = e0 + e1;
        float b = 1.0f + a;
        float D = fmaf(e0, e1, b);        // 1 + e0 + e1 + e0*e1
        float Nm = b + 1.0f;              // 2 + e0 + e1
        float r;
        asm("rcp.approx.f32 %0, %1;" : "=f"(r) : "f"(D));
        if (gp & 1) sumB = fmaf(Nm, r, sumB);
        else        sumA = fmaf(Nm, r, sumA);
    }

    float ks = (sumA + sumB) + 1e-8f;
    float e = __expf(10.0f * (ks - 0.5f));
    out[i] = (1.0f - 1e-9f) / (1.0f + e) + 1e-9f;
}

extern "C" void kernel_launch(void* const* d_in, const int* in_sizes, int n_in,
                              void* d_out, int out_size) {
    const float4* coords4     = (const float4*)d_in[0];
    const float2* coords2     = (const float2*)d_in[0];
    const float*  W_scale     = (const float*)d_in[1];
    const float*  W_shape_var = (const float*)d_in[2];
    const float*  W_rotation  = (const float*)d_in[3];
    const float2* W_offsets   = (const float2*)d_in[4];
    float* out = (float*)d_out;

    gs_fused_kernel<<<GRID, 256>>>(coords4, coords2, W_scale, W_shape_var,
                                   W_rotation, W_offsets, out);
}

// round 13
// speedup vs baseline: 1.1107x; 1.0626x over previous
#include <cuda_runtime.h>
#include <math.h>

// ---------------------------------------------------------------------------
// GaussianSplattingCompliance: N_POINTS=131072, N_G=256
// s(z) = sigmoid(-10(z-1)) = 1/(1+e^{10(z-1)}).  Affine absorbs K=10*log2(e):
//   u = A1*cx+B1*cy+C1, v = A2*cx+B2*cy+C2,  zp = sqrt(uu+vv) = K*z
//   e = 2^{min(zp,73.93) - K}   (clamp keeps pair products finite)
// Pair identity (exact): s0+s1 = (2+e0+e1) * rcp((1+e0)(1+e1))
//   MUFU per gaussian: sqrt(8) + ex2(8) + rcp/2(4) = 20 cyc (tanh path was 24)
// Main kernel: 2 threads/point (gaussian split), packed f32x2 affine math.
// ---------------------------------------------------------------------------

#define N_POINTS 131072
#define N_G      256
#define PRE_BLOCKS 256
#define KK 14.4269504088896341f    // 10 * log2(e)

__device__ unsigned g_enc[4];      // enc(max x), enc(max y), enc(max -x), enc(max -y)
__device__ unsigned g_count;
__device__ float4   g_AB[N_G];     // A1,B1,A2,B2
__device__ float2   g_C[N_G];      // C1,C2

__device__ __forceinline__ unsigned f_enc(float f) {
    unsigned u = __float_as_uint(f);
    return (u & 0x80000000u) ? ~u : (u | 0x80000000u);
}
__device__ __forceinline__ float f_dec(unsigned e) {
    unsigned u = (e & 0x80000000u) ? (e ^ 0x80000000u) : ~e;
    return __uint_as_float(u);
}
__device__ __forceinline__ float sigmoid_f(float x) {
    return 1.0f / (1.0f + expf(-x));
}

// ---------------- fused prologue: minmax + params + scratch reset -----------
__global__ void __launch_bounds__(256)
gs_pre_kernel(const float4* __restrict__ coords4,
              const float*  __restrict__ W_scale,
              const float*  __restrict__ W_shape_var,
              const float*  __restrict__ W_rotation,
              const float2* __restrict__ W_offsets) {
    __shared__ float s_red[8][4];
    __shared__ int   s_last;
    int tid = threadIdx.x;

    float4 q = coords4[blockIdx.x * 256 + tid];
    float mxx = fmaxf(q.x, q.z), mxy = fmaxf(q.y, q.w);
    float nmx = -fminf(q.x, q.z), nmy = -fminf(q.y, q.w);

    #pragma unroll
    for (int o = 16; o > 0; o >>= 1) {
        mxx = fmaxf(mxx, __shfl_xor_sync(0xffffffffu, mxx, o));
        mxy = fmaxf(mxy, __shfl_xor_sync(0xffffffffu, mxy, o));
        nmx = fmaxf(nmx, __shfl_xor_sync(0xffffffffu, nmx, o));
        nmy = fmaxf(nmy, __shfl_xor_sync(0xffffffffu, nmy, o));
    }
    int wid = tid >> 5, lid = tid & 31;
    if (lid == 0) {
        s_red[wid][0] = mxx; s_red[wid][1] = mxy;
        s_red[wid][2] = nmx; s_red[wid][3] = nmy;
    }
    __syncthreads();
    if (tid == 0) {
        float a = s_red[0][0], b = s_red[0][1], c = s_red[0][2], d = s_red[0][3];
        #pragma unroll
        for (int w = 1; w < 8; w++) {
            a = fmaxf(a, s_red[w][0]); b = fmaxf(b, s_red[w][1]);
            c = fmaxf(c, s_red[w][2]); d = fmaxf(d, s_red[w][3]);
        }
        atomicMax(&g_enc[0], f_enc(a));
        atomicMax(&g_enc[1], f_enc(b));
        atomicMax(&g_enc[2], f_enc(c));
        atomicMax(&g_enc[3], f_enc(d));
        __threadfence();
        unsigned done = atomicAdd(&g_count, 1u);
        s_last = (done == PRE_BLOCKS - 1) ? 1 : 0;
    }
    __syncthreads();
    if (!s_last) return;

    float cmaxx = f_dec(atomicMax(&g_enc[0], 0u));
    float cmaxy = f_dec(atomicMax(&g_enc[1], 0u));
    float cminx = -f_dec(atomicMax(&g_enc[2], 0u));
    float cminy = -f_dec(atomicMax(&g_enc[3], 0u));

    float lo_x = cminx - cmaxx * 0.05f, hi_x = cmaxx + cmaxx * 0.05f;
    float lo_y = cminy - cmaxy * 0.05f, hi_y = cmaxy + cmaxy * 0.05f;

    int b = tid;
    float base_scale = (1.5f - 0.05f) * sigmoid_f(W_scale[b]) + 0.05f;
    float ratio      = (3.5f - 0.5f) * sigmoid_f(W_shape_var[b]) + 0.5f;
    const float PI_F = 3.14159265358979323846f;
    float rot        = -0.5f * PI_F + PI_F * sigmoid_f(W_rotation[b]);
    float2 wo = W_offsets[b];
    float ox = lo_x + (hi_x - lo_x) * sigmoid_f(wo.x);
    float oy = lo_y + (hi_y - lo_y) * sigmoid_f(wo.y);

    float inv_s = 1.0f / (base_scale + 1e-8f);
    float sq0 = sqrtf(1.0f / (1.0f + 1e-6f));
    float sq1 = sqrtf(1.0f / (ratio * ratio + 1e-6f));
    float c = cosf(rot), s = sinf(rot);

    float k0 = KK * inv_s * sq0;     // absorb K = 10*log2(e)
    float k1 = KK * inv_s * sq1;
    float A1 =  c * k0, B1 = -s * k0;
    float A2 =  s * k1, B2 =  c * k1;
    float C1 = -(A1 * ox + B1 * oy);
    float C2 = -(A2 * ox + B2 * oy);

    g_AB[b] = make_float4(A1, B1, A2, B2);
    g_C[b]  = make_float2(C1, C2);

    if (tid < 4) g_enc[tid] = 0u;
    if (tid == 0) g_count = 0u;
}

// ------- main kernel: 2 threads/point (split gaussians), f32x2 math ---------

#define FMA2(d, a, b, c) \
    asm("fma.rn.f32x2 %0, %1, %2, %3;" : "=l"(d) : "l"(a), "l"(b), "l"(c))
#define MUL2(d, a, b) \
    asm("mul.rn.f32x2 %0, %1, %2;" : "=l"(d) : "l"(a), "l"(b))
#define PACK2(d, lo, hi) \
    asm("mov.b64 %0, {%1, %2};" : "=l"(d) : "f"(lo), "f"(hi))
#define UNPACK2(lo, hi, s) \
    asm("mov.b64 {%0, %1}, %2;" : "=f"(lo), "=f"(hi) : "l"(s))

#define N_PAIR   (N_G / 2)      // 128 gaussian pairs
#define PTS_BLK  128            // points per block
#define HALF_GP  (N_PAIR / 2)   // 64 pairs per thread-half

__global__ void __launch_bounds__(256)
gs_main_kernel(const float2* __restrict__ coords, float* __restrict__ out) {
    // per gaussian PAIR p (gaussians 2p, 2p+1), 3 x 16B entries:
    //   sP[3p+0] = {A1_e, A1_o, B1_e, B1_o}
    //   sP[3p+1] = {A2_e, A2_o, B2_e, B2_o}
    //   sP[3p+2] = {C1_e, C1_o, C2_e, C2_o}
    __shared__ ulonglong2 sP[N_PAIR * 3];
    __shared__ float s_part[PTS_BLK];
    int t = threadIdx.x;

    if (t < N_PAIR) {
        float4 abE = g_AB[2 * t];
        float4 abO = g_AB[2 * t + 1];
        float2 cE  = g_C[2 * t];
        float2 cO  = g_C[2 * t + 1];
        float4* dst = (float4*)&sP[3 * t];
        dst[0] = make_float4(abE.x, abO.x, abE.y, abO.y);   // A1 pair, B1 pair
        dst[1] = make_float4(abE.z, abO.z, abE.w, abO.w);   // A2 pair, B2 pair
        dst[2] = make_float4(cE.x,  cO.x,  cE.y,  cO.y);    // C1 pair, C2 pair
    }
    __syncthreads();

    int half = t >> 7;                    // 0: pairs 0..63, 1: pairs 64..127
    int tp   = t & (PTS_BLK - 1);         // point slot within block
    int i = blockIdx.x * PTS_BLK + tp;
    float2 p = coords[i];
    unsigned long long cxx, cyy;
    PACK2(cxx, p.x, p.x);
    PACK2(cyy, p.y, p.y);

    const ulonglong2* pp = &sP[half * HALF_GP * 3];
    float sumA = 0.0f, sumB = 0.0f;
    #pragma unroll 8
    for (int gp = 0; gp < HALF_GP; gp++) {
        ulonglong2 q0 = pp[3 * gp + 0];   // {A1 pair, B1 pair}
        ulonglong2 q1 = pp[3 * gp + 1];   // {A2 pair, B2 pair}
        ulonglong2 q2 = pp[3 * gp + 2];   // {C1 pair, C2 pair}
        unsigned long long uu, vv, ss, t1;
        FMA2(t1, q0.y, cyy, q2.x);        // B1*cy + C1
        FMA2(uu, q0.x, cxx, t1);          // A1*cx + ...
        FMA2(t1, q1.y, cyy, q2.y);        // B2*cy + C2
        FMA2(vv, q1.x, cxx, t1);          // A2*cx + ...
        MUL2(t1, vv, vv);
        FMA2(ss, uu, uu, t1);             // {K^2 z^2 even, odd}

        float s0, s1;
        UNPACK2(s0, s1, ss);
        float z0, z1;
        asm("sqrt.approx.f32 %0, %1;" : "=f"(z0) : "f"(s0));   // K*z
        asm("sqrt.approx.f32 %0, %1;" : "=f"(z1) : "f"(s1));
        float m0 = fminf(z0, 73.93f) - KK;    // clamp: e <= 2^59.5
        float m1 = fminf(z1, 73.93f) - KK;
        float e0, e1;
        asm("ex2.approx.f32 %0, %1;" : "=f"(e0) : "f"(m0));    // e^{10(z-1)}
        asm("ex2.approx.f32 %0, %1;" : "=f"(e1) : "f"(m1));

        // s0+s1 = (2+e0+e1) * rcp((1+e0)(1+e1))   [exact identity]
        float a  = e0 + e1;
        float b  = 1.0f + a;
        float D  = fmaf(e0, e1, b);       // (1+e0)(1+e1)
        float Nm = b + 1.0f;              // 2 + e0 + e1
        float r;
        asm("rcp.approx.f32 %0, %1;" : "=f"(r) : "f"(D));
        if (gp & 1) sumB = fmaf(Nm, r, sumB);
        else        sumA = fmaf(Nm, r, sumA);
    }

    float mysum = sumA + sumB;            // sum of s over this half's gaussians
    if (half) s_part[tp] = mysum;
    __syncthreads();
    if (!half) {
        float tot = mysum + s_part[tp];
        float ks = tot + 1e-8f;
        float e = __expf(10.0f * (ks - 0.5f));
        out[i] = (1.0f - 1e-9f) / (1.0f + e) + 1e-9f;
    }
}

extern "C" void kernel_launch(void* const* d_in, const int* in_sizes, int n_in,
                              void* d_out, int out_size) {
    const float4* coords4     = (const float4*)d_in[0];
    const float2* coords2     = (const float2*)d_in[0];
    const float*  W_scale     = (const float*)d_in[1];
    const float*  W_shape_var = (const float*)d_in[2];
    const float*  W_rotation  = (const float*)d_in[3];
    const float2* W_offsets   = (const float2*)d_in[4];
    float* out = (float*)d_out;

    gs_pre_kernel<<<PRE_BLOCKS, 256>>>(coords4, W_scale, W_shape_var,
                                       W_rotation, W_offsets);
    gs_main_kernel<<<N_POINTS / PTS_BLK, 256>>>(coords2, out);
}